// round 1
// baseline (speedup 1.0000x reference)
#include <cuda_runtime.h>
#include <cuda_bf16.h>
#include <math.h>

#define B_      8
#define NSNP    500000
#define NNODE   2000000
#define NG      20000
#define NF      8
#define H1      1024
#define H2      256
#define H3      16
#define BN_EPS  1e-5f

// ---------------- scratch (device globals; no allocation allowed) ----------
__device__ float g_scaled[NSNP * B_];   // [n][b]  16 MB
__device__ float g_sample[NG * B_];     // [g][b]  640 KB
__device__ float g_h1[B_ * H1];         // [b][j]
__device__ float g_h2[B_ * H2];         // [b][j]

// ---------------- K0: zero accumulators ------------------------------------
__global__ void k_zero() {
    int i = blockIdx.x * blockDim.x + threadIdx.x;
    const int n0 = NG * B_;          // 160000
    const int n1 = n0 + B_ * H1;     // +8192
    const int n2 = n1 + B_ * H2;     // +2048
    if (i < n0)            g_sample[i] = 0.f;
    else if (i < n1)       g_h1[i - n0] = 0.f;
    else if (i < n2)       g_h2[i - n1] = 0.f;
}

// ---------------- K1: scaled[n][b] = snp[b][n] * mean_f(filters[f][n]) -----
__global__ void k_scale(const float* __restrict__ snp,
                        const float* __restrict__ filters) {
    int n = blockIdx.x * blockDim.x + threadIdx.x;
    if (n >= NSNP) return;
    float s = 0.f;
#pragma unroll
    for (int f = 0; f < NF; f++) s += filters[(size_t)f * NSNP + n];
    s *= (1.0f / NF);
    float4 a, b;
    a.x = snp[(size_t)0 * NSNP + n] * s;
    a.y = snp[(size_t)1 * NSNP + n] * s;
    a.z = snp[(size_t)2 * NSNP + n] * s;
    a.w = snp[(size_t)3 * NSNP + n] * s;
    b.x = snp[(size_t)4 * NSNP + n] * s;
    b.y = snp[(size_t)5 * NSNP + n] * s;
    b.z = snp[(size_t)6 * NSNP + n] * s;
    b.w = snp[(size_t)7 * NSNP + n] * s;
    float4* o = reinterpret_cast<float4*>(g_scaled + (size_t)n * 8);
    o[0] = a;
    o[1] = b;
}

// ---------------- K2: segmented sum over sorted node_seg --------------------
// Each thread handles 8 consecutive nodes; accumulates in registers while the
// segment id is unchanged, flushes via atomicAdd at boundaries.
__global__ void k_segsum(const int* __restrict__ ids,
                         const int* __restrict__ seg) {
    int t = blockIdx.x * blockDim.x + threadIdx.x;
    int base = t * 8;
    if (base >= NNODE) return;

    int4 s0 = reinterpret_cast<const int4*>(seg)[t * 2];
    int4 s1 = reinterpret_cast<const int4*>(seg)[t * 2 + 1];
    int4 i0 = reinterpret_cast<const int4*>(ids)[t * 2];
    int4 i1 = reinterpret_cast<const int4*>(ids)[t * 2 + 1];
    int sg[8] = {s0.x, s0.y, s0.z, s0.w, s1.x, s1.y, s1.z, s1.w};
    int id[8] = {i0.x, i0.y, i0.z, i0.w, i1.x, i1.y, i1.z, i1.w};

    float acc[8];
#pragma unroll
    for (int b = 0; b < 8; b++) acc[b] = 0.f;
    int cur = sg[0];

#pragma unroll
    for (int k = 0; k < 8; k++) {
        if (sg[k] != cur) {
#pragma unroll
            for (int b = 0; b < 8; b++)
                atomicAdd(&g_sample[(size_t)cur * 8 + b], acc[b]);
            cur = sg[k];
#pragma unroll
            for (int b = 0; b < 8; b++) acc[b] = 0.f;
        }
        const float4* p =
            reinterpret_cast<const float4*>(g_scaled + (size_t)id[k] * 8);
        float4 u = __ldg(p);
        float4 v = __ldg(p + 1);
        acc[0] += u.x; acc[1] += u.y; acc[2] += u.z; acc[3] += u.w;
        acc[4] += v.x; acc[5] += v.y; acc[6] += v.z; acc[7] += v.w;
    }
#pragma unroll
    for (int b = 0; b < 8; b++)
        atomicAdd(&g_sample[(size_t)cur * 8 + b], acc[b]);
}

// ---------------- K3: GEMM1  h1[b][j] += sum_k sample[k][b] * W1[k][j] ------
#define KSPLIT1 160
#define KCHUNK1 125   // 160 * 125 = 20000
__global__ void k_gemm1(const float* __restrict__ W1) {
    __shared__ float4 ssamp[KCHUNK1 * 2];   // sample[k0..k0+125)[0..8)
    int k0 = blockIdx.x * KCHUNK1;
    int t  = threadIdx.x;

    if (t < KCHUNK1 * 2)
        ssamp[t] = reinterpret_cast<const float4*>(g_sample)[k0 * 2 + t];
    __syncthreads();

    int j = t * 4;   // 256 threads * 4 = 1024 columns
    float acc[8][4];
#pragma unroll
    for (int b = 0; b < 8; b++)
#pragma unroll
        for (int c = 0; c < 4; c++) acc[b][c] = 0.f;

    for (int kk = 0; kk < KCHUNK1; kk++) {
        float4 w = __ldg(reinterpret_cast<const float4*>(
            W1 + (size_t)(k0 + kk) * H1 + j));
        float4 sa = ssamp[kk * 2];
        float4 sb = ssamp[kk * 2 + 1];
        float sv[8] = {sa.x, sa.y, sa.z, sa.w, sb.x, sb.y, sb.z, sb.w};
#pragma unroll
        for (int b = 0; b < 8; b++) {
            acc[b][0] = fmaf(sv[b], w.x, acc[b][0]);
            acc[b][1] = fmaf(sv[b], w.y, acc[b][1]);
            acc[b][2] = fmaf(sv[b], w.z, acc[b][2]);
            acc[b][3] = fmaf(sv[b], w.w, acc[b][3]);
        }
    }
#pragma unroll
    for (int b = 0; b < 8; b++)
#pragma unroll
        for (int c = 0; c < 4; c++)
            atomicAdd(&g_h1[b * H1 + j + c], acc[b][c]);
}

// ---------------- K4: BN + ReLU on h1 ---------------------------------------
__global__ void k_bnrelu1(const float* __restrict__ b1,
                          const float* __restrict__ g1,
                          const float* __restrict__ be1) {
    int i = blockIdx.x * blockDim.x + threadIdx.x;
    if (i >= B_ * H1) return;
    int j = i & (H1 - 1);
    float s = g1[j] * rsqrtf(1.0f + BN_EPS);
    float v = (g_h1[i] + b1[j]) * s + be1[j];
    g_h1[i] = fmaxf(v, 0.f);
}

// ---------------- K5: GEMM2  h2[b][j] += sum_k h1r[b][k] * W2[k][j] ----------
#define KSPLIT2 32
#define KCHUNK2 32    // 32 * 32 = 1024
__global__ void k_gemm2(const float* __restrict__ W2) {
    __shared__ float sh[KCHUNK2 * 8];   // [kk][b]
    int k0 = blockIdx.x * KCHUNK2;
    int t  = threadIdx.x;
    // 256 threads load 256 floats: kk = t/8, b = t%8
    sh[t] = g_h1[(t & 7) * H1 + k0 + (t >> 3)];
    __syncthreads();

    int j = t;  // 256 columns
    float acc[8];
#pragma unroll
    for (int b = 0; b < 8; b++) acc[b] = 0.f;
    for (int kk = 0; kk < KCHUNK2; kk++) {
        float w = __ldg(W2 + (size_t)(k0 + kk) * H2 + j);
#pragma unroll
        for (int b = 0; b < 8; b++)
            acc[b] = fmaf(sh[kk * 8 + b], w, acc[b]);
    }
#pragma unroll
    for (int b = 0; b < 8; b++)
        atomicAdd(&g_h2[b * H2 + j], acc[b]);
}

// ---------------- K6: BN+ReLU(h2) -> GEMM3 -> BN+ReLU -> head -> logits -----
__global__ void k_final(const float* __restrict__ b2,
                        const float* __restrict__ g2,
                        const float* __restrict__ be2,
                        const float* __restrict__ W3,
                        const float* __restrict__ b3,
                        const float* __restrict__ g3,
                        const float* __restrict__ be3,
                        const float* __restrict__ Wh1,
                        const float* __restrict__ bh1,
                        const float* __restrict__ gh,
                        const float* __restrict__ beh,
                        const float* __restrict__ Wh2,
                        const float* __restrict__ bh2,
                        float* __restrict__ out) {
    __shared__ float sh2[B_ * H2];      // 2048
    __shared__ float sfeat[B_ * H3];    // 128
    int t = threadIdx.x;

    // Stage A: BN + ReLU on h2
    float sbn = rsqrtf(1.0f + BN_EPS);
    for (int i = t; i < B_ * H2; i += blockDim.x) {
        int j = i & (H2 - 1);
        float v = (g_h2[i] + b2[j]) * (g2[j] * sbn) + be2[j];
        sh2[i] = fmaxf(v, 0.f);
    }
    __syncthreads();

    // Stage B: feat[b][j] = relu(bn(sum_k sh2[b][k] * W3[k][j] + b3[j]))
    if (t < B_ * H3) {
        int b = t >> 4, j = t & 15;
        float acc = 0.f;
        for (int k = 0; k < H2; k++)
            acc = fmaf(sh2[b * H2 + k], W3[(size_t)k * H3 + j], acc);
        float v = (acc + b3[j]) * (g3[j] * sbn) + be3[j];
        sfeat[b * H3 + j] = fmaxf(v, 0.f);
    }
    __syncthreads();

    // Stage C: head — main_feat = feat[:, :15]; m = relu(bn(mf @ Wh1)); logit
    if (t < B_) {
        int b = t;
        float logit = bh2[0];
#pragma unroll
        for (int q = 0; q < 4; q++) {
            float acc = bh1[q];
            for (int p = 0; p < 15; p++)
                acc = fmaf(sfeat[b * H3 + p], Wh1[p * 4 + q], acc);
            float m = fmaxf(acc * (gh[q] * sbn) + beh[q], 0.f);
            logit = fmaf(m, Wh2[q], logit);
        }
        out[b] = logit;
    }
}

// ---------------- launch -----------------------------------------------------
extern "C" void kernel_launch(void* const* d_in, const int* in_sizes, int n_in,
                              void* d_out, int out_size) {
    const float* snp      = (const float*)d_in[0];
    const int*   snp_ids  = (const int*)  d_in[1];
    const int*   node_seg = (const int*)  d_in[2];
    const float* filters  = (const float*)d_in[3];
    const float* W1  = (const float*)d_in[4];
    const float* b1  = (const float*)d_in[5];
    const float* g1  = (const float*)d_in[6];
    const float* be1 = (const float*)d_in[7];
    const float* W2  = (const float*)d_in[8];
    const float* b2  = (const float*)d_in[9];
    const float* g2  = (const float*)d_in[10];
    const float* be2 = (const float*)d_in[11];
    const float* W3  = (const float*)d_in[12];
    const float* b3  = (const float*)d_in[13];
    const float* g3  = (const float*)d_in[14];
    const float* be3 = (const float*)d_in[15];
    const float* Wh1 = (const float*)d_in[16];
    const float* bh1 = (const float*)d_in[17];
    const float* gh  = (const float*)d_in[18];
    const float* beh = (const float*)d_in[19];
    const float* Wh2 = (const float*)d_in[20];
    const float* bh2 = (const float*)d_in[21];
    float* out = (float*)d_out;

    const int ZN = NG * B_ + B_ * H1 + B_ * H2;
    k_zero<<<(ZN + 255) / 256, 256>>>();
    k_scale<<<(NSNP + 255) / 256, 256>>>(snp, filters);
    k_segsum<<<(NNODE / 8 + 255) / 256, 256>>>(snp_ids, node_seg);
    k_gemm1<<<KSPLIT1, 256>>>(W1);
    k_bnrelu1<<<(B_ * H1 + 255) / 256, 256>>>(b1, g1, be1);
    k_gemm2<<<KSPLIT2, 256>>>(W2);
    k_final<<<1, 256>>>(b2, g2, be2, W3, b3, g3, be3,
                        Wh1, bh1, gh, beh, Wh2, bh2, out);
}

// round 2
// speedup vs baseline: 1.0203x; 1.0203x over previous
#include <cuda_runtime.h>
#include <cuda_bf16.h>
#include <math.h>

#define B_      8
#define NSNP    500000
#define NNODE   2000000
#define NG      20000
#define NF      8
#define H1      1024
#define H2      256
#define H3      16
#define BN_EPS  1e-5f

#define KSPLIT1 400
#define KCHUNK1 50     // 400 * 50 = 20000
#define KSPLIT2 32
#define KCHUNK2 32     // 32 * 32 = 1024

// ---------------- scratch (device globals; no allocation allowed) ----------
__device__ float g_scaled[NSNP * B_];            // [n][b]  16 MB
__device__ float g_sample[NG * B_];              // [g][b]  640 KB
__device__ float g_h1p[KSPLIT1 * B_ * H1];       // 13 MB partials
__device__ float g_h1[B_ * H1];                  // post BN+ReLU
__device__ float g_h2p[KSPLIT2 * B_ * H2];       // 256 KB partials

// ---------------- K0: zero g_sample -----------------------------------------
__global__ void k_zero() {
    int i = blockIdx.x * blockDim.x + threadIdx.x;
    if (i < NG * B_ / 4)
        reinterpret_cast<float4*>(g_sample)[i] = make_float4(0.f, 0.f, 0.f, 0.f);
}

// ---------------- K1: scaled[n][b] = snp[b][n] * mean_f(filters[f][n]) -----
// 4 SNPs per thread, fully vectorized.
__global__ void k_scale(const float* __restrict__ snp,
                        const float* __restrict__ filters) {
    int q = blockIdx.x * blockDim.x + threadIdx.x;   // float4 index over n
    if (q >= NSNP / 4) return;
    float4 s = make_float4(0.f, 0.f, 0.f, 0.f);
#pragma unroll
    for (int f = 0; f < NF; f++) {
        float4 v = __ldg(reinterpret_cast<const float4*>(filters) +
                         (size_t)f * (NSNP / 4) + q);
        s.x += v.x; s.y += v.y; s.z += v.z; s.w += v.w;
    }
    const float inv = 1.0f / NF;
    s.x *= inv; s.y *= inv; s.z *= inv; s.w *= inv;

    float4 sv[NF];
#pragma unroll
    for (int b = 0; b < NF; b++)
        sv[b] = __ldg(reinterpret_cast<const float4*>(snp) +
                      (size_t)b * (NSNP / 4) + q);

    int n0 = q * 4;
    float4* o = reinterpret_cast<float4*>(g_scaled + (size_t)n0 * 8);
    // n0+0
    o[0] = make_float4(sv[0].x * s.x, sv[1].x * s.x, sv[2].x * s.x, sv[3].x * s.x);
    o[1] = make_float4(sv[4].x * s.x, sv[5].x * s.x, sv[6].x * s.x, sv[7].x * s.x);
    // n0+1
    o[2] = make_float4(sv[0].y * s.y, sv[1].y * s.y, sv[2].y * s.y, sv[3].y * s.y);
    o[3] = make_float4(sv[4].y * s.y, sv[5].y * s.y, sv[6].y * s.y, sv[7].y * s.y);
    // n0+2
    o[4] = make_float4(sv[0].z * s.z, sv[1].z * s.z, sv[2].z * s.z, sv[3].z * s.z);
    o[5] = make_float4(sv[4].z * s.z, sv[5].z * s.z, sv[6].z * s.z, sv[7].z * s.z);
    // n0+3
    o[6] = make_float4(sv[0].w * s.w, sv[1].w * s.w, sv[2].w * s.w, sv[3].w * s.w);
    o[7] = make_float4(sv[4].w * s.w, sv[5].w * s.w, sv[6].w * s.w, sv[7].w * s.w);
}

// ---------------- K2: segmented sum over sorted node_seg --------------------
__global__ void k_segsum(const int* __restrict__ ids,
                         const int* __restrict__ seg) {
    int t = blockIdx.x * blockDim.x + threadIdx.x;
    if (t * 8 >= NNODE) return;

    int4 s0 = __ldg(reinterpret_cast<const int4*>(seg) + t * 2);
    int4 s1 = __ldg(reinterpret_cast<const int4*>(seg) + t * 2 + 1);
    int4 i0 = __ldg(reinterpret_cast<const int4*>(ids) + t * 2);
    int4 i1 = __ldg(reinterpret_cast<const int4*>(ids) + t * 2 + 1);
    int sg[8] = {s0.x, s0.y, s0.z, s0.w, s1.x, s1.y, s1.z, s1.w};
    int id[8] = {i0.x, i0.y, i0.z, i0.w, i1.x, i1.y, i1.z, i1.w};

    float acc[8];
#pragma unroll
    for (int b = 0; b < 8; b++) acc[b] = 0.f;
    int cur = sg[0];

#pragma unroll
    for (int k = 0; k < 8; k++) {
        if (sg[k] != cur) {
#pragma unroll
            for (int b = 0; b < 8; b++)
                atomicAdd(&g_sample[(size_t)cur * 8 + b], acc[b]);
            cur = sg[k];
#pragma unroll
            for (int b = 0; b < 8; b++) acc[b] = 0.f;
        }
        const float4* p =
            reinterpret_cast<const float4*>(g_scaled + (size_t)id[k] * 8);
        float4 u = __ldg(p);
        float4 v = __ldg(p + 1);
        acc[0] += u.x; acc[1] += u.y; acc[2] += u.z; acc[3] += u.w;
        acc[4] += v.x; acc[5] += v.y; acc[6] += v.z; acc[7] += v.w;
    }
#pragma unroll
    for (int b = 0; b < 8; b++)
        atomicAdd(&g_sample[(size_t)cur * 8 + b], acc[b]);
}

// ---------------- K3: GEMM1 partials: h1p[s][b][j] = sum_k samp[k][b]*W1[k][j]
__global__ void k_gemm1(const float* __restrict__ W1) {
    __shared__ float4 ssamp[KCHUNK1 * 2];   // sample[k0..k0+50)[0..8)
    int blk = blockIdx.x;
    int k0  = blk * KCHUNK1;
    int t   = threadIdx.x;

    if (t < KCHUNK1 * 2)
        ssamp[t] = reinterpret_cast<const float4*>(g_sample)[k0 * 2 + t];
    __syncthreads();

    int j = t * 4;   // 256 threads * 4 = 1024 columns
    float acc[8][4];
#pragma unroll
    for (int b = 0; b < 8; b++)
#pragma unroll
        for (int c = 0; c < 4; c++) acc[b][c] = 0.f;

#pragma unroll 5
    for (int kk = 0; kk < KCHUNK1; kk++) {
        float4 w = __ldg(reinterpret_cast<const float4*>(
            W1 + (size_t)(k0 + kk) * H1 + j));
        float4 sa = ssamp[kk * 2];
        float4 sb = ssamp[kk * 2 + 1];
        float sv[8] = {sa.x, sa.y, sa.z, sa.w, sb.x, sb.y, sb.z, sb.w};
#pragma unroll
        for (int b = 0; b < 8; b++) {
            acc[b][0] = fmaf(sv[b], w.x, acc[b][0]);
            acc[b][1] = fmaf(sv[b], w.y, acc[b][1]);
            acc[b][2] = fmaf(sv[b], w.z, acc[b][2]);
            acc[b][3] = fmaf(sv[b], w.w, acc[b][3]);
        }
    }
    float* dst = g_h1p + (size_t)blk * B_ * H1;
#pragma unroll
    for (int b = 0; b < 8; b++)
        *reinterpret_cast<float4*>(dst + b * H1 + j) =
            make_float4(acc[b][0], acc[b][1], acc[b][2], acc[b][3]);
}

// ---------------- K4: reduce partials + BN + ReLU -> g_h1 -------------------
__global__ void k_reduce1(const float* __restrict__ b1,
                          const float* __restrict__ g1,
                          const float* __restrict__ be1) {
    int i = blockIdx.x * blockDim.x + threadIdx.x;
    if (i >= B_ * H1) return;
    float sum = 0.f;
#pragma unroll 8
    for (int s = 0; s < KSPLIT1; s++)
        sum += g_h1p[(size_t)s * (B_ * H1) + i];
    int j = i & (H1 - 1);
    float sc = g1[j] * rsqrtf(1.0f + BN_EPS);
    float v = (sum + b1[j]) * sc + be1[j];
    g_h1[i] = fmaxf(v, 0.f);
}

// ---------------- K5: GEMM2 partials ----------------------------------------
__global__ void k_gemm2(const float* __restrict__ W2) {
    __shared__ float sh[KCHUNK2 * 8];   // [kk][b]
    int blk = blockIdx.x;
    int k0  = blk * KCHUNK2;
    int t   = threadIdx.x;
    sh[t] = g_h1[(t & 7) * H1 + k0 + (t >> 3)];
    __syncthreads();

    int j = t;  // 256 columns
    float acc[8];
#pragma unroll
    for (int b = 0; b < 8; b++) acc[b] = 0.f;
#pragma unroll 8
    for (int kk = 0; kk < KCHUNK2; kk++) {
        float w = __ldg(W2 + (size_t)(k0 + kk) * H2 + j);
#pragma unroll
        for (int b = 0; b < 8; b++)
            acc[b] = fmaf(sh[kk * 8 + b], w, acc[b]);
    }
    float* dst = g_h2p + (size_t)blk * B_ * H2;
#pragma unroll
    for (int b = 0; b < 8; b++)
        dst[b * H2 + j] = acc[b];
}

// ---------------- K6: reduce h2 partials + BN+ReLU -> GEMM3 -> head ---------
__global__ void k_final(const float* __restrict__ b2,
                        const float* __restrict__ g2,
                        const float* __restrict__ be2,
                        const float* __restrict__ W3,
                        const float* __restrict__ b3,
                        const float* __restrict__ g3,
                        const float* __restrict__ be3,
                        const float* __restrict__ Wh1,
                        const float* __restrict__ bh1,
                        const float* __restrict__ gh,
                        const float* __restrict__ beh,
                        const float* __restrict__ Wh2,
                        const float* __restrict__ bh2,
                        float* __restrict__ out) {
    __shared__ float sh2[B_ * H2];      // 2048
    __shared__ float sfeat[B_ * H3];    // 128
    int t = threadIdx.x;
    float sbn = rsqrtf(1.0f + BN_EPS);

    // Stage A: reduce partials + BN + ReLU on h2
    for (int i = t; i < B_ * H2; i += blockDim.x) {
        float sum = 0.f;
#pragma unroll 8
        for (int s = 0; s < KSPLIT2; s++)
            sum += g_h2p[(size_t)s * (B_ * H2) + i];
        int j = i & (H2 - 1);
        float v = (sum + b2[j]) * (g2[j] * sbn) + be2[j];
        sh2[i] = fmaxf(v, 0.f);
    }
    __syncthreads();

    // Stage B: feat[b][j] = relu(bn(sum_k sh2[b][k] * W3[k][j] + b3[j]))
    if (t < B_ * H3) {
        int b = t >> 4, j = t & 15;
        float acc = 0.f;
        for (int k = 0; k < H2; k++)
            acc = fmaf(sh2[b * H2 + k], W3[(size_t)k * H3 + j], acc);
        float v = (acc + b3[j]) * (g3[j] * sbn) + be3[j];
        sfeat[b * H3 + j] = fmaxf(v, 0.f);
    }
    __syncthreads();

    // Stage C: head
    if (t < B_) {
        int b = t;
        float logit = bh2[0];
#pragma unroll
        for (int q = 0; q < 4; q++) {
            float acc = bh1[q];
            for (int p = 0; p < 15; p++)
                acc = fmaf(sfeat[b * H3 + p], Wh1[p * 4 + q], acc);
            float m = fmaxf(acc * (gh[q] * sbn) + beh[q], 0.f);
            logit = fmaf(m, Wh2[q], logit);
        }
        out[b] = logit;
    }
}

// ---------------- launch -----------------------------------------------------
extern "C" void kernel_launch(void* const* d_in, const int* in_sizes, int n_in,
                              void* d_out, int out_size) {
    const float* snp      = (const float*)d_in[0];
    const int*   snp_ids  = (const int*)  d_in[1];
    const int*   node_seg = (const int*)  d_in[2];
    const float* filters  = (const float*)d_in[3];
    const float* W1  = (const float*)d_in[4];
    const float* b1  = (const float*)d_in[5];
    const float* g1  = (const float*)d_in[6];
    const float* be1 = (const float*)d_in[7];
    const float* W2  = (const float*)d_in[8];
    const float* b2  = (const float*)d_in[9];
    const float* g2  = (const float*)d_in[10];
    const float* be2 = (const float*)d_in[11];
    const float* W3  = (const float*)d_in[12];
    const float* b3  = (const float*)d_in[13];
    const float* g3  = (const float*)d_in[14];
    const float* be3 = (const float*)d_in[15];
    const float* Wh1 = (const float*)d_in[16];
    const float* bh1 = (const float*)d_in[17];
    const float* gh  = (const float*)d_in[18];
    const float* beh = (const float*)d_in[19];
    const float* Wh2 = (const float*)d_in[20];
    const float* bh2 = (const float*)d_in[21];
    float* out = (float*)d_out;

    k_zero<<<(NG * B_ / 4 + 255) / 256, 256>>>();
    k_scale<<<(NSNP / 4 + 255) / 256, 256>>>(snp, filters);
    k_segsum<<<(NNODE / 8 + 255) / 256, 256>>>(snp_ids, node_seg);
    k_gemm1<<<KSPLIT1, 256>>>(W1);
    k_reduce1<<<(B_ * H1 + 255) / 256, 256>>>(b1, g1, be1);
    k_gemm2<<<KSPLIT2, 256>>>(W2);
    k_final<<<1, 256>>>(b2, g2, be2, W3, b3, g3, be3,
                        Wh1, bh1, gh, beh, Wh2, bh2, out);
}

// round 3
// speedup vs baseline: 1.5122x; 1.4822x over previous
#include <cuda_runtime.h>
#include <cuda_bf16.h>
#include <math.h>

#define B_      8
#define NSNP    500000
#define NNODE   2000000
#define NG      20000
#define NF      8
#define H1      1024
#define H2      256
#define H3      16
#define BN_EPS  1e-5f

#define KSPLIT1 400
#define KCHUNK1 50     // 400 * 50 = 20000
#define JSPLIT1 2
#define KSPLIT2 32
#define KCHUNK2 32     // 32 * 32 = 1024

// ---------------- scratch ----------------------------------------------------
__device__ float g_scaled[NSNP * B_];            // [n][b]  16 MB
__device__ float g_sample[NG * B_];              // [g][b]  640 KB
__device__ float g_h1p[KSPLIT1 * B_ * H1];       // 13 MB partials
__device__ float g_h1[B_ * H1];                  // post BN+ReLU
__device__ float g_h2p[KSPLIT2 * B_ * H2];       // 256 KB partials
__device__ float g_h2[B_ * H2];                  // post BN+ReLU

// ---------------- K1: fused zero(g_sample) + scale ---------------------------
#define SCALE_BLOCKS ((NSNP / 4 + 255) / 256)          // 489
#define ZERO_BLOCKS  ((NG * B_ / 4 + 255) / 256)       // 157
__global__ void k_prep(const float* __restrict__ snp,
                       const float* __restrict__ filters) {
    if (blockIdx.x >= SCALE_BLOCKS) {
        int i = (blockIdx.x - SCALE_BLOCKS) * blockDim.x + threadIdx.x;
        if (i < NG * B_ / 4)
            reinterpret_cast<float4*>(g_sample)[i] =
                make_float4(0.f, 0.f, 0.f, 0.f);
        return;
    }
    int q = blockIdx.x * blockDim.x + threadIdx.x;   // float4 index over n
    if (q >= NSNP / 4) return;
    float4 s = make_float4(0.f, 0.f, 0.f, 0.f);
#pragma unroll
    for (int f = 0; f < NF; f++) {
        float4 v = __ldg(reinterpret_cast<const float4*>(filters) +
                         (size_t)f * (NSNP / 4) + q);
        s.x += v.x; s.y += v.y; s.z += v.z; s.w += v.w;
    }
    const float inv = 1.0f / NF;
    s.x *= inv; s.y *= inv; s.z *= inv; s.w *= inv;

    float4 sv[NF];
#pragma unroll
    for (int b = 0; b < NF; b++)
        sv[b] = __ldg(reinterpret_cast<const float4*>(snp) +
                      (size_t)b * (NSNP / 4) + q);

    int n0 = q * 4;
    float4* o = reinterpret_cast<float4*>(g_scaled + (size_t)n0 * 8);
    o[0] = make_float4(sv[0].x * s.x, sv[1].x * s.x, sv[2].x * s.x, sv[3].x * s.x);
    o[1] = make_float4(sv[4].x * s.x, sv[5].x * s.x, sv[6].x * s.x, sv[7].x * s.x);
    o[2] = make_float4(sv[0].y * s.y, sv[1].y * s.y, sv[2].y * s.y, sv[3].y * s.y);
    o[3] = make_float4(sv[4].y * s.y, sv[5].y * s.y, sv[6].y * s.y, sv[7].y * s.y);
    o[4] = make_float4(sv[0].z * s.z, sv[1].z * s.z, sv[2].z * s.z, sv[3].z * s.z);
    o[5] = make_float4(sv[4].z * s.z, sv[5].z * s.z, sv[6].z * s.z, sv[7].z * s.z);
    o[6] = make_float4(sv[0].w * s.w, sv[1].w * s.w, sv[2].w * s.w, sv[3].w * s.w);
    o[7] = make_float4(sv[4].w * s.w, sv[5].w * s.w, sv[6].w * s.w, sv[7].w * s.w);
}

// ---------------- K2: warp-cooperative segmented sum -------------------------
// lane = sub*8 + b. Subgroup `sub` (8 lanes) handles 16 contiguous nodes;
// lane b accumulates batch b. One coalesced 32B gather per node.
#define NODES_PER_SUB 16
#define NODES_PER_WARP 64
__global__ void k_segsum(const int* __restrict__ ids,
                         const int* __restrict__ seg) {
    int gwarp = (blockIdx.x * blockDim.x + threadIdx.x) >> 5;
    int lane  = threadIdx.x & 31;
    int sub   = lane >> 3;
    int b     = lane & 7;
    long wbase = (long)gwarp * NODES_PER_WARP;
    if (wbase >= NNODE) return;                   // whole-warp granular
    long base = wbase + (long)sub * NODES_PER_SUB;

    // coalesced stream of ids/seg: lane covers node base+b and base+8+b
    int i0 = __ldg(ids + base + b);
    int i1 = __ldg(ids + base + 8 + b);
    int s0 = __ldg(seg + base + b);
    int s1 = __ldg(seg + base + 8 + b);

    // gather phase: all 16 node values in flight at once
    float v[NODES_PER_SUB];
#pragma unroll
    for (int k = 0; k < NODES_PER_SUB; k++) {
        int src = sub * 8 + (k & 7);
        int idk = __shfl_sync(0xffffffffu, (k < 8) ? i0 : i1, src);
        v[k] = __ldg(g_scaled + (size_t)idk * 8 + b);
    }

    // accumulate phase with run-length flush
    int cur = __shfl_sync(0xffffffffu, s0, sub * 8);
    float acc = 0.f;
#pragma unroll
    for (int k = 0; k < NODES_PER_SUB; k++) {
        int src = sub * 8 + (k & 7);
        int sgk = __shfl_sync(0xffffffffu, (k < 8) ? s0 : s1, src);
        if (sgk != cur) {
            atomicAdd(&g_sample[(size_t)cur * 8 + b], acc);
            acc = 0.f;
            cur = sgk;
        }
        acc += v[k];
    }
    atomicAdd(&g_sample[(size_t)cur * 8 + b], acc);
}

// ---------------- K3: GEMM1 partials (k-split x j-split) ---------------------
// block bx: blk = bx/2 (k-split), jh = bx%2 (columns [jh*512, jh*512+512))
__global__ void k_gemm1(const float* __restrict__ W1) {
    __shared__ float ssamp[KCHUNK1][8];
    int bx  = blockIdx.x;
    int blk = bx >> 1;
    int jh  = bx & 1;
    int k0  = blk * KCHUNK1;
    int t   = threadIdx.x;

    if (t < KCHUNK1 * 2)
        reinterpret_cast<float4*>(ssamp)[t] =
            reinterpret_cast<const float4*>(g_sample)[k0 * 2 + t];
    __syncthreads();

    int j = jh * 512 + t * 2;
    float acc[8][2];
#pragma unroll
    for (int b = 0; b < 8; b++) { acc[b][0] = 0.f; acc[b][1] = 0.f; }

#pragma unroll 10
    for (int kk = 0; kk < KCHUNK1; kk++) {
        float2 w = __ldg(reinterpret_cast<const float2*>(
            W1 + (size_t)(k0 + kk) * H1 + j));
#pragma unroll
        for (int b = 0; b < 8; b++) {
            float sv = ssamp[kk][b];
            acc[b][0] = fmaf(sv, w.x, acc[b][0]);
            acc[b][1] = fmaf(sv, w.y, acc[b][1]);
        }
    }
    float* dst = g_h1p + (size_t)blk * (B_ * H1);
#pragma unroll
    for (int b = 0; b < 8; b++)
        *reinterpret_cast<float2*>(dst + b * H1 + j) =
            make_float2(acc[b][0], acc[b][1]);
}

// ---------------- K4: parallel reduce of h1 partials + BN + ReLU -------------
// 256 blocks; block handles 32 outputs; 8 warps split the 400 splits.
__global__ void k_reduce1(const float* __restrict__ b1,
                          const float* __restrict__ g1,
                          const float* __restrict__ be1) {
    __shared__ float red[8][32];
    int lane = threadIdx.x & 31;
    int w    = threadIdx.x >> 5;
    int o    = blockIdx.x * 32 + lane;     // 0..8191
    float sum = 0.f;
#pragma unroll 5
    for (int s = w; s < KSPLIT1; s += 8)
        sum += __ldg(g_h1p + (size_t)s * (B_ * H1) + o);
    red[w][lane] = sum;
    __syncthreads();
    if (w == 0) {
        float tot = 0.f;
#pragma unroll
        for (int x = 0; x < 8; x++) tot += red[x][lane];
        int j = o & (H1 - 1);
        float sc = g1[j] * rsqrtf(1.0f + BN_EPS);
        g_h1[o] = fmaxf((tot + b1[j]) * sc + be1[j], 0.f);
    }
}

// ---------------- K5: GEMM2 partials ----------------------------------------
__global__ void k_gemm2(const float* __restrict__ W2) {
    __shared__ float sh[KCHUNK2 * 8];   // [kk][b]
    int blk = blockIdx.x;
    int k0  = blk * KCHUNK2;
    int t   = threadIdx.x;
    sh[t] = g_h1[(t & 7) * H1 + k0 + (t >> 3)];
    __syncthreads();

    int j = t;
    float acc[8];
#pragma unroll
    for (int b = 0; b < 8; b++) acc[b] = 0.f;
#pragma unroll 8
    for (int kk = 0; kk < KCHUNK2; kk++) {
        float w = __ldg(W2 + (size_t)(k0 + kk) * H2 + j);
#pragma unroll
        for (int b = 0; b < 8; b++)
            acc[b] = fmaf(sh[kk * 8 + b], w, acc[b]);
    }
    float* dst = g_h2p + (size_t)blk * (B_ * H2);
#pragma unroll
    for (int b = 0; b < 8; b++)
        dst[b * H2 + j] = acc[b];
}

// ---------------- K6: reduce h2 partials + BN + ReLU -------------------------
__global__ void k_reduce2(const float* __restrict__ b2,
                          const float* __restrict__ g2,
                          const float* __restrict__ be2) {
    int i = blockIdx.x * blockDim.x + threadIdx.x;
    if (i >= B_ * H2) return;
    float sum = 0.f;
#pragma unroll 8
    for (int s = 0; s < KSPLIT2; s++)
        sum += __ldg(g_h2p + (size_t)s * (B_ * H2) + i);
    int j = i & (H2 - 1);
    float sc = g2[j] * rsqrtf(1.0f + BN_EPS);
    g_h2[i] = fmaxf((sum + b2[j]) * sc + be2[j], 0.f);
}

// ---------------- K7: GEMM3 -> BN+ReLU -> head -> logits ---------------------
__global__ void k_final(const float* __restrict__ W3,
                        const float* __restrict__ b3,
                        const float* __restrict__ g3,
                        const float* __restrict__ be3,
                        const float* __restrict__ Wh1,
                        const float* __restrict__ bh1,
                        const float* __restrict__ gh,
                        const float* __restrict__ beh,
                        const float* __restrict__ Wh2,
                        const float* __restrict__ bh2,
                        float* __restrict__ out) {
    __shared__ float sh2[B_ * H2];
    __shared__ float sfeat[B_ * H3];
    int t = threadIdx.x;
    float sbn = rsqrtf(1.0f + BN_EPS);

    for (int i = t; i < B_ * H2; i += blockDim.x)
        sh2[i] = g_h2[i];
    __syncthreads();

    if (t < B_ * H3) {
        int b = t >> 4, j = t & 15;
        float acc = 0.f;
        for (int k = 0; k < H2; k++)
            acc = fmaf(sh2[b * H2 + k], W3[(size_t)k * H3 + j], acc);
        float v = (acc + b3[j]) * (g3[j] * sbn) + be3[j];
        sfeat[b * H3 + j] = fmaxf(v, 0.f);
    }
    __syncthreads();

    if (t < B_) {
        int b = t;
        float logit = bh2[0];
#pragma unroll
        for (int q = 0; q < 4; q++) {
            float acc = bh1[q];
            for (int p = 0; p < 15; p++)
                acc = fmaf(sfeat[b * H3 + p], Wh1[p * 4 + q], acc);
            float m = fmaxf(acc * (gh[q] * sbn) + beh[q], 0.f);
            logit = fmaf(m, Wh2[q], logit);
        }
        out[b] = logit;
    }
}

// ---------------- launch -----------------------------------------------------
extern "C" void kernel_launch(void* const* d_in, const int* in_sizes, int n_in,
                              void* d_out, int out_size) {
    const float* snp      = (const float*)d_in[0];
    const int*   snp_ids  = (const int*)  d_in[1];
    const int*   node_seg = (const int*)  d_in[2];
    const float* filters  = (const float*)d_in[3];
    const float* W1  = (const float*)d_in[4];
    const float* b1  = (const float*)d_in[5];
    const float* g1  = (const float*)d_in[6];
    const float* be1 = (const float*)d_in[7];
    const float* W2  = (const float*)d_in[8];
    const float* b2  = (const float*)d_in[9];
    const float* g2  = (const float*)d_in[10];
    const float* be2 = (const float*)d_in[11];
    const float* W3  = (const float*)d_in[12];
    const float* b3  = (const float*)d_in[13];
    const float* g3  = (const float*)d_in[14];
    const float* be3 = (const float*)d_in[15];
    const float* Wh1 = (const float*)d_in[16];
    const float* bh1 = (const float*)d_in[17];
    const float* gh  = (const float*)d_in[18];
    const float* beh = (const float*)d_in[19];
    const float* Wh2 = (const float*)d_in[20];
    const float* bh2 = (const float*)d_in[21];
    float* out = (float*)d_out;

    k_prep<<<SCALE_BLOCKS + ZERO_BLOCKS, 256>>>(snp, filters);
    int segsum_blocks = (NNODE / NODES_PER_WARP * 32 + 255) / 256;  // 3907
    k_segsum<<<segsum_blocks, 256>>>(snp_ids, node_seg);
    k_gemm1<<<KSPLIT1 * JSPLIT1, 256>>>(W1);
    k_reduce1<<<(B_ * H1) / 32, 256>>>(b1, g1, be1);
    k_gemm2<<<KSPLIT2, 256>>>(W2);
    k_reduce2<<<(B_ * H2 + 255) / 256, 256>>>(b2, g2, be2);
    k_final<<<1, 256>>>(W3, b3, g3, be3, Wh1, bh1, gh, beh, Wh2, bh2, out);
}

// round 4
// speedup vs baseline: 1.5128x; 1.0004x over previous
#include <cuda_runtime.h>
#include <cuda_bf16.h>
#include <math.h>

#define B_      8
#define NSNP    500000
#define NNODE   2000000
#define NG      20000
#define NF      8
#define H1      1024
#define H2      256
#define H3      16
#define BN_EPS  1e-5f

#define KSPLIT1 400
#define KCHUNK1 50     // 400 * 50 = 20000
#define JSPLIT1 2
#define KSPLIT2 32
#define KCHUNK2 32     // 32 * 32 = 1024

// ---------------- scratch ----------------------------------------------------
__device__ float g_scaled[NSNP * B_];            // [n][b]  16 MB
__device__ float g_sample[NG * B_];              // [g][b]  640 KB
__device__ float g_h1p[KSPLIT1 * B_ * H1];       // 13 MB partials
__device__ float g_h1[B_ * H1];                  // post BN+ReLU
__device__ float g_h2p[KSPLIT2 * B_ * H2];       // 256 KB partials
__device__ float g_h2[B_ * H2];                  // post BN+ReLU

// ---------------- K1: fused zero(g_sample) + scale ---------------------------
#define SCALE_BLOCKS ((NSNP / 4 + 255) / 256)          // 489
#define ZERO_BLOCKS  ((NG * B_ / 4 + 255) / 256)       // 157
__global__ void k_prep(const float* __restrict__ snp,
                       const float* __restrict__ filters) {
    if (blockIdx.x >= SCALE_BLOCKS) {
        int i = (blockIdx.x - SCALE_BLOCKS) * blockDim.x + threadIdx.x;
        if (i < NG * B_ / 4)
            reinterpret_cast<float4*>(g_sample)[i] =
                make_float4(0.f, 0.f, 0.f, 0.f);
        return;
    }
    int q = blockIdx.x * blockDim.x + threadIdx.x;   // float4 index over n
    if (q >= NSNP / 4) return;
    float4 s = make_float4(0.f, 0.f, 0.f, 0.f);
#pragma unroll
    for (int f = 0; f < NF; f++) {
        float4 v = __ldg(reinterpret_cast<const float4*>(filters) +
                         (size_t)f * (NSNP / 4) + q);
        s.x += v.x; s.y += v.y; s.z += v.z; s.w += v.w;
    }
    const float inv = 1.0f / NF;
    s.x *= inv; s.y *= inv; s.z *= inv; s.w *= inv;

    float4 sv[NF];
#pragma unroll
    for (int b = 0; b < NF; b++)
        sv[b] = __ldg(reinterpret_cast<const float4*>(snp) +
                      (size_t)b * (NSNP / 4) + q);

    int n0 = q * 4;
    float4* o = reinterpret_cast<float4*>(g_scaled + (size_t)n0 * 8);
    o[0] = make_float4(sv[0].x * s.x, sv[1].x * s.x, sv[2].x * s.x, sv[3].x * s.x);
    o[1] = make_float4(sv[4].x * s.x, sv[5].x * s.x, sv[6].x * s.x, sv[7].x * s.x);
    o[2] = make_float4(sv[0].y * s.y, sv[1].y * s.y, sv[2].y * s.y, sv[3].y * s.y);
    o[3] = make_float4(sv[4].y * s.y, sv[5].y * s.y, sv[6].y * s.y, sv[7].y * s.y);
    o[4] = make_float4(sv[0].z * s.z, sv[1].z * s.z, sv[2].z * s.z, sv[3].z * s.z);
    o[5] = make_float4(sv[4].z * s.z, sv[5].z * s.z, sv[6].z * s.z, sv[7].z * s.z);
    o[6] = make_float4(sv[0].w * s.w, sv[1].w * s.w, sv[2].w * s.w, sv[3].w * s.w);
    o[7] = make_float4(sv[4].w * s.w, sv[5].w * s.w, sv[6].w * s.w, sv[7].w * s.w);
}

// ---------------- K2: shfl-free warp-cooperative segmented sum ---------------
// lane = sub*8 + b. Subgroup `sub` (8 lanes) handles 16 contiguous nodes;
// lane b owns batch b. Each lane loads the subgroup's 16 ids/segs directly
// (int4, L1-broadcast across the 8 lanes), so all 16 gathers are independent.
#define NODES_PER_SUB 16
#define NODES_PER_WARP 64
__global__ void k_segsum(const int* __restrict__ ids,
                         const int* __restrict__ seg) {
    int gwarp = (blockIdx.x * blockDim.x + threadIdx.x) >> 5;
    int lane  = threadIdx.x & 31;
    int sub   = lane >> 3;
    int b     = lane & 7;
    long wbase = (long)gwarp * NODES_PER_WARP;
    if (wbase >= NNODE) return;                   // whole-warp granular
    long base = wbase + (long)sub * NODES_PER_SUB;

    const int4* ip = reinterpret_cast<const int4*>(ids + base);
    const int4* sp = reinterpret_cast<const int4*>(seg + base);
    int4 i0 = __ldg(ip),     i1 = __ldg(ip + 1);
    int4 i2 = __ldg(ip + 2), i3 = __ldg(ip + 3);
    int4 s0 = __ldg(sp),     s1 = __ldg(sp + 1);
    int4 s2 = __ldg(sp + 2), s3 = __ldg(sp + 3);
    int id[16] = {i0.x, i0.y, i0.z, i0.w, i1.x, i1.y, i1.z, i1.w,
                  i2.x, i2.y, i2.z, i2.w, i3.x, i3.y, i3.z, i3.w};
    int sg[16] = {s0.x, s0.y, s0.z, s0.w, s1.x, s1.y, s1.z, s1.w,
                  s2.x, s2.y, s2.z, s2.w, s3.x, s3.y, s3.z, s3.w};

    // gather phase: 16 independent loads in flight
    float v[16];
#pragma unroll
    for (int k = 0; k < 16; k++)
        v[k] = __ldg(g_scaled + (size_t)id[k] * 8 + b);

    // accumulate phase with run-length flush
    int cur = sg[0];
    float acc = 0.f;
#pragma unroll
    for (int k = 0; k < 16; k++) {
        if (sg[k] != cur) {
            atomicAdd(&g_sample[(size_t)cur * 8 + b], acc);
            acc = 0.f;
            cur = sg[k];
        }
        acc += v[k];
    }
    atomicAdd(&g_sample[(size_t)cur * 8 + b], acc);
}

// ---------------- K3: GEMM1 partials (k-split x j-split) ---------------------
__global__ void k_gemm1(const float* __restrict__ W1) {
    __shared__ float ssamp[KCHUNK1][8];
    int bx  = blockIdx.x;
    int blk = bx >> 1;
    int jh  = bx & 1;
    int k0  = blk * KCHUNK1;
    int t   = threadIdx.x;

    if (t < KCHUNK1 * 2)
        reinterpret_cast<float4*>(ssamp)[t] =
            reinterpret_cast<const float4*>(g_sample)[k0 * 2 + t];
    __syncthreads();

    int j = jh * 512 + t * 2;
    float acc[8][2];
#pragma unroll
    for (int b = 0; b < 8; b++) { acc[b][0] = 0.f; acc[b][1] = 0.f; }

#pragma unroll 10
    for (int kk = 0; kk < KCHUNK1; kk++) {
        float2 w = __ldg(reinterpret_cast<const float2*>(
            W1 + (size_t)(k0 + kk) * H1 + j));
#pragma unroll
        for (int b = 0; b < 8; b++) {
            float sv = ssamp[kk][b];
            acc[b][0] = fmaf(sv, w.x, acc[b][0]);
            acc[b][1] = fmaf(sv, w.y, acc[b][1]);
        }
    }
    float* dst = g_h1p + (size_t)blk * (B_ * H1);
#pragma unroll
    for (int b = 0; b < 8; b++)
        *reinterpret_cast<float2*>(dst + b * H1 + j) =
            make_float2(acc[b][0], acc[b][1]);
}

// ---------------- K4: vectorized parallel reduce of h1 partials + BN + ReLU --
// 64 blocks. Block covers 32 float4 outputs (128 floats). 8 groups of 32
// threads each reduce 50 splits with float4 loads (512B/warp coalesced).
__global__ void k_reduce1(const float* __restrict__ b1,
                          const float* __restrict__ g1,
                          const float* __restrict__ be1) {
    __shared__ float4 sred[256];
    int t   = threadIdx.x;
    int col = t & 31;     // float4 column within block
    int grp = t >> 5;     // 0..7 -> split group
    int ob  = blockIdx.x * 32 + col;     // global float4 index (0..2047)
    const float4* P = reinterpret_cast<const float4*>(g_h1p);

    float4 acc = make_float4(0.f, 0.f, 0.f, 0.f);
    int s0 = grp * (KSPLIT1 / 8);
#pragma unroll 10
    for (int s = s0; s < s0 + KSPLIT1 / 8; s++) {
        float4 v = __ldg(P + (size_t)s * (B_ * H1 / 4) + ob);
        acc.x += v.x; acc.y += v.y; acc.z += v.z; acc.w += v.w;
    }
    sred[t] = acc;
    __syncthreads();
    if (grp == 0) {
        float4 tot = sred[col];
#pragma unroll
        for (int x = 1; x < 8; x++) {
            float4 v = sred[x * 32 + col];
            tot.x += v.x; tot.y += v.y; tot.z += v.z; tot.w += v.w;
        }
        int o = ob * 4;
        float r[4] = {tot.x, tot.y, tot.z, tot.w};
        float ro[4];
#pragma unroll
        for (int c = 0; c < 4; c++) {
            int j = (o + c) & (H1 - 1);
            float sc = g1[j] * rsqrtf(1.0f + BN_EPS);
            ro[c] = fmaxf((r[c] + b1[j]) * sc + be1[j], 0.f);
        }
        *reinterpret_cast<float4*>(g_h1 + o) =
            make_float4(ro[0], ro[1], ro[2], ro[3]);
    }
}

// ---------------- K5: GEMM2 partials ----------------------------------------
__global__ void k_gemm2(const float* __restrict__ W2) {
    __shared__ float sh[KCHUNK2 * 8];   // [kk][b]
    int blk = blockIdx.x;
    int k0  = blk * KCHUNK2;
    int t   = threadIdx.x;
    sh[t] = g_h1[(t & 7) * H1 + k0 + (t >> 3)];
    __syncthreads();

    int j = t;
    float acc[8];
#pragma unroll
    for (int b = 0; b < 8; b++) acc[b] = 0.f;
#pragma unroll 8
    for (int kk = 0; kk < KCHUNK2; kk++) {
        float w = __ldg(W2 + (size_t)(k0 + kk) * H2 + j);
#pragma unroll
        for (int b = 0; b < 8; b++)
            acc[b] = fmaf(sh[kk * 8 + b], w, acc[b]);
    }
    float* dst = g_h2p + (size_t)blk * (B_ * H2);
#pragma unroll
    for (int b = 0; b < 8; b++)
        dst[b * H2 + j] = acc[b];
}

// ---------------- K6: reduce h2 partials + BN + ReLU -------------------------
__global__ void k_reduce2(const float* __restrict__ b2,
                          const float* __restrict__ g2,
                          const float* __restrict__ be2) {
    int i = blockIdx.x * blockDim.x + threadIdx.x;
    if (i >= B_ * H2) return;
    float sum = 0.f;
#pragma unroll 8
    for (int s = 0; s < KSPLIT2; s++)
        sum += __ldg(g_h2p + (size_t)s * (B_ * H2) + i);
    int j = i & (H2 - 1);
    float sc = g2[j] * rsqrtf(1.0f + BN_EPS);
    g_h2[i] = fmaxf((sum + b2[j]) * sc + be2[j], 0.f);
}

// ---------------- K7: GEMM3 -> BN+ReLU -> head -> logits ---------------------
__global__ void k_final(const float* __restrict__ W3,
                        const float* __restrict__ b3,
                        const float* __restrict__ g3,
                        const float* __restrict__ be3,
                        const float* __restrict__ Wh1,
                        const float* __restrict__ bh1,
                        const float* __restrict__ gh,
                        const float* __restrict__ beh,
                        const float* __restrict__ Wh2,
                        const float* __restrict__ bh2,
                        float* __restrict__ out) {
    __shared__ float sh2[B_ * H2];
    __shared__ float sfeat[B_ * H3];
    int t = threadIdx.x;
    float sbn = rsqrtf(1.0f + BN_EPS);

    for (int i = t; i < B_ * H2; i += blockDim.x)
        sh2[i] = g_h2[i];
    __syncthreads();

    if (t < B_ * H3) {
        int b = t >> 4, j = t & 15;
        float acc = 0.f;
        for (int k = 0; k < H2; k++)
            acc = fmaf(sh2[b * H2 + k], W3[(size_t)k * H3 + j], acc);
        float v = (acc + b3[j]) * (g3[j] * sbn) + be3[j];
        sfeat[b * H3 + j] = fmaxf(v, 0.f);
    }
    __syncthreads();

    if (t < B_) {
        int b = t;
        float logit = bh2[0];
#pragma unroll
        for (int q = 0; q < 4; q++) {
            float acc = bh1[q];
            for (int p = 0; p < 15; p++)
                acc = fmaf(sfeat[b * H3 + p], Wh1[p * 4 + q], acc);
            float m = fmaxf(acc * (gh[q] * sbn) + beh[q], 0.f);
            logit = fmaf(m, Wh2[q], logit);
        }
        out[b] = logit;
    }
}

// ---------------- launch -----------------------------------------------------
extern "C" void kernel_launch(void* const* d_in, const int* in_sizes, int n_in,
                              void* d_out, int out_size) {
    const float* snp      = (const float*)d_in[0];
    const int*   snp_ids  = (const int*)  d_in[1];
    const int*   node_seg = (const int*)  d_in[2];
    const float* filters  = (const float*)d_in[3];
    const float* W1  = (const float*)d_in[4];
    const float* b1  = (const float*)d_in[5];
    const float* g1  = (const float*)d_in[6];
    const float* be1 = (const float*)d_in[7];
    const float* W2  = (const float*)d_in[8];
    const float* b2  = (const float*)d_in[9];
    const float* g2  = (const float*)d_in[10];
    const float* be2 = (const float*)d_in[11];
    const float* W3  = (const float*)d_in[12];
    const float* b3  = (const float*)d_in[13];
    const float* g3  = (const float*)d_in[14];
    const float* be3 = (const float*)d_in[15];
    const float* Wh1 = (const float*)d_in[16];
    const float* bh1 = (const float*)d_in[17];
    const float* gh  = (const float*)d_in[18];
    const float* beh = (const float*)d_in[19];
    const float* Wh2 = (const float*)d_in[20];
    const float* bh2 = (const float*)d_in[21];
    float* out = (float*)d_out;

    k_prep<<<SCALE_BLOCKS + ZERO_BLOCKS, 256>>>(snp, filters);
    int segsum_blocks = (NNODE / NODES_PER_WARP * 32 + 255) / 256;  // 3907
    k_segsum<<<segsum_blocks, 256>>>(snp_ids, node_seg);
    k_gemm1<<<KSPLIT1 * JSPLIT1, 256>>>(W1);
    k_reduce1<<<(B_ * H1 / 4) / 32, 256>>>(b1, g1, be1);
    k_gemm2<<<KSPLIT2, 256>>>(W2);
    k_reduce2<<<(B_ * H2 + 255) / 256, 256>>>(b2, g2, be2);
    k_final<<<1, 256>>>(W3, b3, g3, be3, Wh1, bh1, gh, beh, Wh2, bh2, out);
}